// round 3
// baseline (speedup 1.0000x reference)
#include <cuda_runtime.h>
#include <cuda_bf16.h>

// Echo state network.
//   x (256,28,28) f32, W_in (128,28), W_res (128,128), W_out (10,128), b_out (10)
//   proj = x.reshape(7168,28) @ W_in^T                      (7168,128)
//   h_{t+1} = tanh(proj_t + W_res @ h_t)  t = 0..7167  (single serial state)
//   h_last[b] = h after step b*28+27 ; out = h_last @ W_out^T + b_out (256,10)

#define HIDDEN   128
#define T_STEPS  7168
#define SEQ      28
#define BATCH    256
#define NOUT     10

typedef unsigned long long ull;

__device__ float g_proj[T_STEPS * HIDDEN];   // 3.67 MB -> lives in L2 during scan
__device__ float g_hlast[BATCH * HIDDEN];

// -------- packed f32x2 helpers (sm_100+) --------
__device__ __forceinline__ ull pack2(float lo, float hi) {
    ull r;
    asm("mov.b64 %0, {%1, %2};" : "=l"(r) : "f"(lo), "f"(hi));
    return r;
}
__device__ __forceinline__ void unpack2(ull v, float& lo, float& hi) {
    asm("mov.b64 {%0, %1}, %2;" : "=f"(lo), "=f"(hi) : "l"(v));
}
__device__ __forceinline__ ull ffma2(ull a, ull b, ull c) {
    ull d;
    asm("fma.rn.f32x2 %0, %1, %2, %3;" : "=l"(d) : "l"(a), "l"(b), "l"(c));
    return d;
}
__device__ __forceinline__ ull fadd2(ull a, ull b) {
    ull d;
    asm("add.rn.f32x2 %0, %1, %2;" : "=l"(d) : "l"(a), "l"(b));
    return d;
}
__device__ __forceinline__ float ex2_approx(float x) {
    float y;
    asm("ex2.approx.f32 %0, %1;" : "=f"(y) : "f"(x));
    return y;
}

// tanh via e^{2x}: (e-1)/(e+1). No clamp needed: |u| <= |p|max + ||w_row|| * ||h||_2
// <= ~4 + 0.9*sqrt(128) ~= 14, and e^28 is finite. ~1e-7 abs err.
__device__ __forceinline__ float tanh_fast(float x) {
    float e = ex2_approx(x * 2.885390081777927f);   // e^{2x} = 2^{2x*log2(e)}
    return __fdividef(e - 1.0f, e + 1.0f);
}

// ============================================================
// Kernel 1: proj = x @ W_in^T.  112 blocks x 128 threads, 64 timesteps/block.
// Thread i holds W_in row i in registers; x tile staged in smem (broadcast reads).
// ============================================================
__global__ __launch_bounds__(128) void proj_kernel(
    const float* __restrict__ x, const float* __restrict__ W_in)
{
    __shared__ float sx[64 * SEQ];          // 7 KB x tile
    const int i  = threadIdx.x;
    const int t0 = blockIdx.x * 64;

    // my W_in row -> registers (28 floats; small, L2-cached across blocks)
    float w[SEQ];
    #pragma unroll
    for (int d = 0; d < SEQ; d++) w[d] = __ldg(&W_in[i * SEQ + d]);

    // coalesced stage of x[t0..t0+64) rows
    for (int k = i; k < 64 * SEQ; k += 128) sx[k] = x[t0 * SEQ + k];
    __syncthreads();

    #pragma unroll 4
    for (int tl = 0; tl < 64; tl++) {
        const float* xr = &sx[tl * SEQ];    // broadcast across lanes
        float a = 0.f;
        #pragma unroll
        for (int d = 0; d < SEQ; d++) a = fmaf(xr[d], w[d], a);
        g_proj[(t0 + tl) * HIDDEN + i] = a; // coalesced
    }
}

// ============================================================
// Kernel 2: the sequential scan. ONE block, 128 threads (1 warp per SMSP).
// Thread i owns row i of W_res in 64 packed f32x2 registers.
// h double-buffered in smem; explicit depth-8 LDS software pipeline
// (prefetch distance = 2 groups = 32 issue cycles > 29-cycle LDS latency).
// ============================================================
__global__ __launch_bounds__(128, 1) void scan_kernel(
    const float* __restrict__ W_res)
{
    __shared__ __align__(16) float hbuf[2][HIDDEN];
    const int i = threadIdx.x;

    // my W_res row, packed: w[2k] = (W[i][4k],W[i][4k+1]), w[2k+1] = (W[i][4k+2],W[i][4k+3])
    ull w[64];
    {
        const float2* wrow = (const float2*)(W_res + i * HIDDEN);
        #pragma unroll
        for (int j = 0; j < 64; j++) {
            float2 v = wrow[j];
            w[j] = pack2(v.x, v.y);
        }
    }
    hbuf[0][i] = 0.f;
    __syncthreads();

    // proj prefetch pipeline (depth 2; covers L2 latency)
    float pc = g_proj[i];
    float pn = g_proj[HIDDEN + i];
    int cnt = 0, batch = 0;

    for (int t = 0; t < T_STEPS; t++) {
        float pf = (t + 2 < T_STEPS) ? g_proj[(t + 2) * HIDDEN + i] : 0.f;

        const ulonglong2* h2 = (const ulonglong2*)hbuf[t & 1];

        // ---- depth-8 pipelined matvec: 32 LDS.128 + 64 FFMA2, 4 accumulators ----
        ull a0 = pack2(pc, 0.f), a1 = 0ull, a2 = 0ull, a3 = 0ull;

        ulonglong2 c0 = h2[0], c1 = h2[1], c2 = h2[2], c3 = h2[3];
        ulonglong2 c4 = h2[4], c5 = h2[5], c6 = h2[6], c7 = h2[7];

        #pragma unroll
        for (int g = 0; g < 8; g++) {       // group g consumes c0..c3 (8 ffma2)
            ulonglong2 n0, n1, n2, n3;
            if (g + 2 < 8) {                // prefetch group g+2 (static after unroll)
                n0 = h2[4 * (g + 2) + 0];
                n1 = h2[4 * (g + 2) + 1];
                n2 = h2[4 * (g + 2) + 2];
                n3 = h2[4 * (g + 2) + 3];
            }
            a0 = ffma2(w[8 * g + 0], c0.x, a0);
            a1 = ffma2(w[8 * g + 1], c0.y, a1);
            a2 = ffma2(w[8 * g + 2], c1.x, a2);
            a3 = ffma2(w[8 * g + 3], c1.y, a3);
            a0 = ffma2(w[8 * g + 4], c2.x, a0);
            a1 = ffma2(w[8 * g + 5], c2.y, a1);
            a2 = ffma2(w[8 * g + 6], c3.x, a2);
            a3 = ffma2(w[8 * g + 7], c3.y, a3);
            c0 = c4; c1 = c5; c2 = c6; c3 = c7;
            if (g + 2 < 8) { c4 = n0; c5 = n1; c6 = n2; c7 = n3; }
        }

        // ---- reduce (2 levels) + tanh ----
        ull s01 = fadd2(a0, a1);
        ull s23 = fadd2(a2, a3);
        ull st  = fadd2(s01, s23);
        float lo, hi;
        unpack2(st, lo, hi);
        float hn = tanh_fast(lo + hi);

        hbuf[(t + 1) & 1][i] = hn;

        if (++cnt == SEQ) {                 // end of a batch: record state (rare)
            cnt = 0;
            g_hlast[batch * HIDDEN + i] = hn;
            batch++;
        }

        pc = pn;
        pn = pf;
        __syncthreads();
    }
}

// ============================================================
// Kernel 3: out = h_last @ W_out^T + b_out   (256 x 10)
// ============================================================
__global__ __launch_bounds__(128) void out_kernel(
    const float* __restrict__ W_out, const float* __restrict__ b_out,
    float* __restrict__ out)
{
    int tid = blockIdx.x * blockDim.x + threadIdx.x;
    if (tid >= BATCH * NOUT) return;
    int b = tid / NOUT;
    int o = tid % NOUT;
    const float* hr = g_hlast + b * HIDDEN;
    const float* wr = W_out + o * HIDDEN;
    float a = b_out[o];
    #pragma unroll 8
    for (int h = 0; h < HIDDEN; h++)
        a = fmaf(hr[h], wr[h], a);
    out[tid] = a;
}

// ============================================================
extern "C" void kernel_launch(void* const* d_in, const int* in_sizes, int n_in,
                              void* d_out, int out_size)
{
    const float* x     = (const float*)d_in[0];
    const float* W_in  = (const float*)d_in[1];
    const float* W_res = (const float*)d_in[2];
    const float* W_out = (const float*)d_in[3];
    const float* b_out = (const float*)d_in[4];
    float* out = (float*)d_out;

    proj_kernel<<<T_STEPS / 64, 128>>>(x, W_in);
    scan_kernel<<<1, 128>>>(W_res);
    out_kernel<<<(BATCH * NOUT + 127) / 128, 128>>>(W_out, b_out, out);
}

// round 4
// speedup vs baseline: 1.0738x; 1.0738x over previous
#include <cuda_runtime.h>
#include <cuda_bf16.h>

// Echo state network, fully fused into ONE kernel.
//   x (256,28,28) f32, W_in (128,28), W_res (128,128), W_out (10,128), b_out (10)
//   proj = x.reshape(7168,28) @ W_in^T                      (7168,128)
//   h_{t+1} = tanh(proj_t + W_res @ h_t)  t = 0..7167  (single serial state)
//   h_last[b] = h after step b*28+27 ; out = h_last @ W_out^T + b_out (256,10)
//
// Phase 1: all 112 blocks compute proj slices (64 timesteps each).
// Grid-sync: atomic counter; blocks != 0 exit. Block 0 then runs the serial
// scan (128 threads, W_res row per thread in registers) and the output head.

#define HIDDEN   128
#define T_STEPS  7168
#define SEQ      28
#define BATCH    256
#define NOUT     10
#define NBLK     112        // T_STEPS / 64

typedef unsigned long long ull;

__device__ float g_proj[T_STEPS * HIDDEN];   // 3.67 MB -> L2-resident during scan
__device__ float g_hlast[BATCH * HIDDEN];
__device__ int   g_sync;                     // zero-init; reset by block 0 each run

// -------- packed f32x2 helpers (sm_100+) --------
__device__ __forceinline__ ull pack2(float lo, float hi) {
    ull r;
    asm("mov.b64 %0, {%1, %2};" : "=l"(r) : "f"(lo), "f"(hi));
    return r;
}
__device__ __forceinline__ void unpack2(ull v, float& lo, float& hi) {
    asm("mov.b64 {%0, %1}, %2;" : "=f"(lo), "=f"(hi) : "l"(v));
}
__device__ __forceinline__ ull ffma2(ull a, ull b, ull c) {
    ull d;
    asm("fma.rn.f32x2 %0, %1, %2, %3;" : "=l"(d) : "l"(a), "l"(b), "l"(c));
    return d;
}
__device__ __forceinline__ ull fadd2(ull a, ull b) {
    ull d;
    asm("add.rn.f32x2 %0, %1, %2;" : "=l"(d) : "l"(a), "l"(b));
    return d;
}
__device__ __forceinline__ float ex2_approx(float x) {
    float y;
    asm("ex2.approx.f32 %0, %1;" : "=f"(y) : "f"(x));
    return y;
}

// K2 = 2*log2(e). W_res and proj are PRE-SCALED by K2, so the pre-activation
// we accumulate is already u' = K2*(p + W h); tanh(x) = (2^{u'}-1)/(2^{u'}+1).
// |x| <= ~14 provably (||W h|| <= 0.9*sqrt(128)+|p|max), so 2^{u'} finite.
#define K2SCALE 2.885390081777927f

__global__ __launch_bounds__(128, 1) void esn_fused_kernel(
    const float* __restrict__ x,     const float* __restrict__ W_in,
    const float* __restrict__ W_res, const float* __restrict__ W_out,
    const float* __restrict__ b_out, float* __restrict__ out)
{
    __shared__ float sx[64 * SEQ];                 // 7 KB x tile (proj phase)
    __shared__ __align__(16) float hbuf[2][HIDDEN];

    const int i   = threadIdx.x;
    const int blk = blockIdx.x;

    // ================= Phase 1: proj slice =================
    {
        const int t0 = blk * 64;
        float wi[SEQ];
        #pragma unroll
        for (int d = 0; d < SEQ; d++) wi[d] = __ldg(&W_in[i * SEQ + d]);

        for (int k = i; k < 64 * SEQ; k += 128) sx[k] = x[t0 * SEQ + k];
        __syncthreads();

        #pragma unroll 4
        for (int tl = 0; tl < 64; tl++) {
            const float* xr = &sx[tl * SEQ];       // broadcast
            float a = 0.f;
            #pragma unroll
            for (int d = 0; d < SEQ; d++) a = fmaf(xr[d], wi[d], a);
            g_proj[(t0 + tl) * HIDDEN + i] = a;    // coalesced
        }
    }

    // release: make proj stores visible, then signal
    __threadfence();
    __syncthreads();
    if (i == 0) atomicAdd(&g_sync, 1);
    if (blk != 0) return;

    // ============ Block 0: load W_res row (overlaps with the spin) ============
    ull w[64];
    {
        const float2* wrow = (const float2*)(W_res + i * HIDDEN);
        #pragma unroll
        for (int j = 0; j < 64; j++) {
            float2 v = wrow[j];
            w[j] = pack2(v.x * K2SCALE, v.y * K2SCALE);
        }
    }

    // acquire: wait for all 112 blocks, then reset counter for next graph replay
    if (i == 0) {
        while (atomicAdd(&g_sync, 0) < NBLK) { }
        atomicExch(&g_sync, 0);
    }
    __syncthreads();
    __threadfence();

    // ================= Phase 2: serial scan =================
    hbuf[0][i] = 0.f;
    __syncthreads();

    float pc = __ldcg(&g_proj[i]) * K2SCALE;
    float pn = __ldcg(&g_proj[HIDDEN + i]) * K2SCALE;
    int cnt = 0, batch = 0;

    for (int t = 0; t < T_STEPS; t++) {
        float pf = 0.f;
        if (t + 2 < T_STEPS) pf = __ldcg(&g_proj[(t + 2) * HIDDEN + i]) * K2SCALE;

        const ulonglong2* h2 = (const ulonglong2*)hbuf[t & 1];

        // 32 x LDS.128 + 64 x f32x2-FMA, 4 accumulators
        ull a0 = pack2(pc, 0.f), a1 = 0ull, a2 = 0ull, a3 = 0ull;
        #pragma unroll
        for (int j = 0; j < 8; j++) {
            ulonglong2 v0 = h2[4 * j + 0];
            ulonglong2 v1 = h2[4 * j + 1];
            ulonglong2 v2 = h2[4 * j + 2];
            ulonglong2 v3 = h2[4 * j + 3];
            a0 = ffma2(w[8 * j + 0], v0.x, a0);
            a1 = ffma2(w[8 * j + 1], v0.y, a1);
            a2 = ffma2(w[8 * j + 2], v1.x, a2);
            a3 = ffma2(w[8 * j + 3], v1.y, a3);
            a0 = ffma2(w[8 * j + 4], v2.x, a0);
            a1 = ffma2(w[8 * j + 5], v2.y, a1);
            a2 = ffma2(w[8 * j + 6], v3.x, a2);
            a3 = ffma2(w[8 * j + 7], v3.y, a3);
        }

        // reduce + tanh (input already scaled by K2)
        ull s01 = fadd2(a0, a1);
        ull s23 = fadd2(a2, a3);
        ull st  = fadd2(s01, s23);
        float lo, hi;
        unpack2(st, lo, hi);
        float e  = ex2_approx(lo + hi);            // = e^{2u}
        float hn = __fdividef(e - 1.0f, e + 1.0f);

        hbuf[(t + 1) & 1][i] = hn;

        if (++cnt == SEQ) {                        // end of batch: record state
            cnt = 0;
            g_hlast[batch * HIDDEN + i] = hn;
            batch++;
        }

        pc = pn;
        pn = pf;
        __syncthreads();
    }

    // ================= Phase 3: output head =================
    // (g_hlast stores by this block are visible after __syncthreads)
    __syncthreads();
    for (int e = i; e < BATCH * NOUT; e += 128) {
        int b = e / NOUT;
        int o = e - b * NOUT;
        const float* hr = g_hlast + b * HIDDEN;
        const float* wr = W_out + o * HIDDEN;
        float a = __ldg(&b_out[o]);
        #pragma unroll 8
        for (int h = 0; h < HIDDEN; h++)
            a = fmaf(hr[h], __ldg(&wr[h]), a);
        out[e] = a;
    }
}

extern "C" void kernel_launch(void* const* d_in, const int* in_sizes, int n_in,
                              void* d_out, int out_size)
{
    const float* x     = (const float*)d_in[0];
    const float* W_in  = (const float*)d_in[1];
    const float* W_res = (const float*)d_in[2];
    const float* W_out = (const float*)d_in[3];
    const float* b_out = (const float*)d_in[4];
    float* out = (float*)d_out;

    esn_fused_kernel<<<NBLK, 128>>>(x, W_in, W_res, W_out, b_out, out);
}